// round 1
// baseline (speedup 1.0000x reference)
#include <cuda_runtime.h>
#include <cuda_bf16.h>

// Problem constants
#define B  4
#define C  64
#define H  256
#define W  256
#define HW (H*W)              // 65536
#define NPIX (B*HW)           // 262144 source pixels
#define NIMG (C*HW)           // 4194304 image elements

// Scratch: the accumulated spike image [C,H,W] (summed over batch) + reduction accumulators.
__device__ float  g_image[NIMG];   // 16 MB, lives in L2 during the run
__device__ double g_acc[2];        // [0]=sum, [1]=sumsq

// ---------------------------------------------------------------------------
// Kernel 1: zero the image + accumulators
// ---------------------------------------------------------------------------
__global__ void zero_kernel() {
    int i = blockIdx.x * blockDim.x + threadIdx.x;
    float4* p = reinterpret_cast<float4*>(g_image);
    if (i < NIMG / 4) p[i] = make_float4(0.f, 0.f, 0.f, 0.f);
    if (i == 0) { g_acc[0] = 0.0; g_acc[1] = 0.0; }
}

// ---------------------------------------------------------------------------
// Kernel 2: forward bilinear splat.
// One thread per source pixel (b,y,x); loops over the 64 time bins.
// Warp lanes = consecutive x, so spike loads are coalesced (128B/warp per c)
// and atomic targets are mostly within the same / adjacent cache lines.
// ---------------------------------------------------------------------------
__global__ void __launch_bounds__(256) splat_kernel(
    const float* __restrict__ flow,
    const float* __restrict__ spike)
{
    int idx = blockIdx.x * blockDim.x + threadIdx.x;
    if (idx >= NPIX) return;

    int b = idx >> 16;          // / HW
    int p = idx & (HW - 1);     // % HW
    int y = p >> 8;             // / W
    int x = p & (W - 1);        // % W

    const float u = flow[(size_t)b * 2 * HW + p];
    const float v = flow[(size_t)b * 2 * HW + HW + p];
    const float* sp = spike + (size_t)b * C * HW + p;

    const float xf = (float)x;
    const float yf = (float)y;

    #pragma unroll 4
    for (int c = 0; c < C; ++c) {
        const float val = __ldg(sp + (size_t)c * HW);
        const float s   = ((float)c - 31.5f) * (1.0f / 64.0f);

        const float xn = fmaf(u, s, xf);
        const float yn = fmaf(v, s, yf);
        const float x0f = floorf(xn);
        const float y0f = floorf(yn);
        const float wx = xn - x0f;
        const float wy = yn - y0f;
        const int x0 = (int)x0f;
        const int y0 = (int)y0f;

        const float vwx  = val * wx;          // val*wx
        const float vmwx = val - vwx;         // val*(1-wx)

        float* plane = g_image + (size_t)c * HW;

        const bool xi0 = (x0 >= 0) & (x0 < W);
        const bool xi1 = (x0 >= -1) & (x0 < W - 1);

        if (y0 >= 0 && y0 < H) {
            float* row = plane + y0 * W;
            if (xi0) atomicAdd(row + x0,     vmwx * (1.0f - wy));
            if (xi1) atomicAdd(row + x0 + 1, vwx  * (1.0f - wy));
        }
        if (y0 >= -1 && y0 < H - 1) {
            float* row = plane + (y0 + 1) * W;
            if (xi0) atomicAdd(row + x0,     vmwx * wy);
            if (xi1) atomicAdd(row + x0 + 1, vwx  * wy);
        }
    }
}

// ---------------------------------------------------------------------------
// Kernel 3: sum and sum-of-squares over the image (double accumulation).
// ---------------------------------------------------------------------------
__global__ void __launch_bounds__(256) reduce_kernel() {
    double s = 0.0, s2 = 0.0;
    const int stride = gridDim.x * blockDim.x;
    for (int i = blockIdx.x * blockDim.x + threadIdx.x; i < NIMG; i += stride) {
        float v = g_image[i];
        s  += (double)v;
        s2 += (double)v * (double)v;
    }
    // warp reduce
    #pragma unroll
    for (int o = 16; o > 0; o >>= 1) {
        s  += __shfl_down_sync(0xFFFFFFFFu, s,  o);
        s2 += __shfl_down_sync(0xFFFFFFFFu, s2, o);
    }
    __shared__ double sh[2][8];
    int lane = threadIdx.x & 31;
    int wid  = threadIdx.x >> 5;
    if (lane == 0) { sh[0][wid] = s; sh[1][wid] = s2; }
    __syncthreads();
    if (wid == 0) {
        s  = (lane < 8) ? sh[0][lane] : 0.0;
        s2 = (lane < 8) ? sh[1][lane] : 0.0;
        #pragma unroll
        for (int o = 4; o > 0; o >>= 1) {
            s  += __shfl_down_sync(0xFFFFFFFFu, s,  o);
            s2 += __shfl_down_sync(0xFFFFFFFFu, s2, o);
        }
        if (lane == 0) {
            atomicAdd(&g_acc[0], s);
            atomicAdd(&g_acc[1], s2);
        }
    }
}

// ---------------------------------------------------------------------------
// Kernel 4: final loss = -var(image, ddof=1)
// ---------------------------------------------------------------------------
__global__ void final_kernel(float* out) {
    const double sum   = g_acc[0];
    const double sumsq = g_acc[1];
    const double Nd    = (double)NIMG;
    const double var   = (sumsq - sum * sum / Nd) / (Nd - 1.0);
    out[0] = (float)(-var);
}

// ---------------------------------------------------------------------------
extern "C" void kernel_launch(void* const* d_in, const int* in_sizes, int n_in,
                              void* d_out, int out_size)
{
    // Identify inputs by size (flow = 4*2*256*256 = 524288, spike = 16777216)
    const float* flow;
    const float* spike;
    if (in_sizes[0] == 2 * NPIX) {
        flow  = (const float*)d_in[0];
        spike = (const float*)d_in[1];
    } else {
        flow  = (const float*)d_in[1];
        spike = (const float*)d_in[0];
    }
    float* out = (float*)d_out;

    zero_kernel<<<(NIMG / 4 + 255) / 256, 256>>>();
    splat_kernel<<<(NPIX + 255) / 256, 256>>>(flow, spike);
    reduce_kernel<<<1024, 256>>>();
    final_kernel<<<1, 1>>>(out);
}

// round 2
// speedup vs baseline: 2.0156x; 2.0156x over previous
#include <cuda_runtime.h>
#include <cuda_bf16.h>

// Problem constants
#define B  4
#define C  64
#define H  256
#define W  256
#define HW (H*W)              // 65536
#define NPIX (B*HW)           // 262144 source pixels
#define NIMG (C*HW)           // 4194304 image elements

// Scratch image in [H, W, C] layout: index = (y*W + x)*C + c.
// 4-channel groups are contiguous & 16B aligned -> float4 vector atomics.
__device__ float  g_image[NIMG];   // 16 MB
__device__ double g_acc[2];        // [0]=sum, [1]=sumsq

// ---------------------------------------------------------------------------
// Kernel 1: zero image + accumulators
// ---------------------------------------------------------------------------
__global__ void zero_kernel() {
    int i = blockIdx.x * blockDim.x + threadIdx.x;
    float4* p = reinterpret_cast<float4*>(g_image);
    if (i < NIMG / 4) p[i] = make_float4(0.f, 0.f, 0.f, 0.f);
    if (i == 0) { g_acc[0] = 0.0; g_acc[1] = 0.0; }
}

// ---------------------------------------------------------------------------
// Kernel 2: forward bilinear splat, 4 channels at a time.
// Displacement u*s_c is monotonic in c, so a 4-channel group shares the same
// corner cell iff the endpoint channels do. Fast path: 4 float4 atomics.
// Slow path (cell straddle, ~10-15%): scalar atomics per channel.
// ---------------------------------------------------------------------------
__global__ void __launch_bounds__(256) splat_kernel(
    const float* __restrict__ flow,
    const float* __restrict__ spike)
{
    int idx = blockIdx.x * blockDim.x + threadIdx.x;
    if (idx >= NPIX) return;

    const int b = idx >> 16;          // / HW
    const int p = idx & (HW - 1);     // % HW
    const int y = p >> 8;             // / W
    const int x = p & (W - 1);        // % W

    const float u = flow[(size_t)b * 2 * HW + p];
    const float v = flow[(size_t)b * 2 * HW + HW + p];
    const float* sp = spike + (size_t)b * C * HW + p;

    const float xf = (float)x;
    const float yf = (float)y;

    #pragma unroll
    for (int g = 0; g < C / 4; ++g) {
        float val[4], wx[4], wy[4];
        int   x0[4], y0[4];

        #pragma unroll
        for (int k = 0; k < 4; ++k) {
            const int c = g * 4 + k;
            val[k] = __ldg(sp + (size_t)c * HW);
            const float s  = ((float)c - 31.5f) * (1.0f / 64.0f);
            const float xn = fmaf(u, s, xf);
            const float yn = fmaf(v, s, yf);
            const float fx = floorf(xn);
            const float fy = floorf(yn);
            wx[k] = xn - fx;
            wy[k] = yn - fy;
            x0[k] = (int)fx;
            y0[k] = (int)fy;
        }

        // Monotonic displacement: endpoints determine uniformity.
        if ((x0[0] == x0[3]) & (y0[0] == y0[3])) {
            const int X0 = x0[0], Y0 = y0[0];

            float4 w00, w10, w01, w11;
            {
                float a0 = val[0] * wx[0], b0 = val[0] - a0;   // a=val*wx, b=val*(1-wx)
                float a1 = val[1] * wx[1], b1 = val[1] - a1;
                float a2 = val[2] * wx[2], b2 = val[2] - a2;
                float a3 = val[3] * wx[3], b3 = val[3] - a3;
                float q0 = 1.0f - wy[0], q1 = 1.0f - wy[1];
                float q2 = 1.0f - wy[2], q3 = 1.0f - wy[3];
                w00 = make_float4(b0*q0,    b1*q1,    b2*q2,    b3*q3);
                w10 = make_float4(a0*q0,    a1*q1,    a2*q2,    a3*q3);
                w01 = make_float4(b0*wy[0], b1*wy[1], b2*wy[2], b3*wy[3]);
                w11 = make_float4(a0*wy[0], a1*wy[1], a2*wy[2], a3*wy[3]);
            }

            const bool vx0 = (X0 >= 0)  & (X0 < W);
            const bool vx1 = (X0 >= -1) & (X0 < W - 1);
            const bool vy0 = (Y0 >= 0)  & (Y0 < H);
            const bool vy1 = (Y0 >= -1) & (Y0 < H - 1);

            float* base = g_image + g * 4;
            if (vy0) {
                float* row = base + (size_t)(Y0 * W) * C;
                if (vx0) atomicAdd(reinterpret_cast<float4*>(row + (size_t)X0 * C),       w00);
                if (vx1) atomicAdd(reinterpret_cast<float4*>(row + (size_t)(X0 + 1) * C), w10);
            }
            if (vy1) {
                float* row = base + (size_t)((Y0 + 1) * W) * C;
                if (vx0) atomicAdd(reinterpret_cast<float4*>(row + (size_t)X0 * C),       w01);
                if (vx1) atomicAdd(reinterpret_cast<float4*>(row + (size_t)(X0 + 1) * C), w11);
            }
        } else {
            // Slow path: per-channel scalar atomics.
            #pragma unroll
            for (int k = 0; k < 4; ++k) {
                const int X0 = x0[k], Y0 = y0[k];
                const float a = val[k] * wx[k];       // val*wx
                const float bb = val[k] - a;          // val*(1-wx)
                const float q = 1.0f - wy[k];

                const bool vx0 = (X0 >= 0)  & (X0 < W);
                const bool vx1 = (X0 >= -1) & (X0 < W - 1);

                float* chan = g_image + g * 4 + k;
                if (Y0 >= 0 && Y0 < H) {
                    float* row = chan + (size_t)(Y0 * W) * C;
                    if (vx0) atomicAdd(row + (size_t)X0 * C,       bb * q);
                    if (vx1) atomicAdd(row + (size_t)(X0 + 1) * C, a  * q);
                }
                if (Y0 >= -1 && Y0 < H - 1) {
                    float* row = chan + (size_t)((Y0 + 1) * W) * C;
                    if (vx0) atomicAdd(row + (size_t)X0 * C,       bb * wy[k]);
                    if (vx1) atomicAdd(row + (size_t)(X0 + 1) * C, a  * wy[k]);
                }
            }
        }
    }
}

// ---------------------------------------------------------------------------
// Kernel 3: sum and sum-of-squares over the image (double accumulation).
// ---------------------------------------------------------------------------
__global__ void __launch_bounds__(256) reduce_kernel() {
    double s = 0.0, s2 = 0.0;
    const int stride = gridDim.x * blockDim.x;
    const float4* img4 = reinterpret_cast<const float4*>(g_image);
    for (int i = blockIdx.x * blockDim.x + threadIdx.x; i < NIMG / 4; i += stride) {
        float4 v = img4[i];
        s  += (double)v.x + (double)v.y + (double)v.z + (double)v.w;
        s2 += (double)v.x * v.x + (double)v.y * v.y
            + (double)v.z * v.z + (double)v.w * v.w;
    }
    #pragma unroll
    for (int o = 16; o > 0; o >>= 1) {
        s  += __shfl_down_sync(0xFFFFFFFFu, s,  o);
        s2 += __shfl_down_sync(0xFFFFFFFFu, s2, o);
    }
    __shared__ double sh[2][8];
    int lane = threadIdx.x & 31;
    int wid  = threadIdx.x >> 5;
    if (lane == 0) { sh[0][wid] = s; sh[1][wid] = s2; }
    __syncthreads();
    if (wid == 0) {
        s  = (lane < 8) ? sh[0][lane] : 0.0;
        s2 = (lane < 8) ? sh[1][lane] : 0.0;
        #pragma unroll
        for (int o = 4; o > 0; o >>= 1) {
            s  += __shfl_down_sync(0xFFFFFFFFu, s,  o);
            s2 += __shfl_down_sync(0xFFFFFFFFu, s2, o);
        }
        if (lane == 0) {
            atomicAdd(&g_acc[0], s);
            atomicAdd(&g_acc[1], s2);
        }
    }
}

// ---------------------------------------------------------------------------
// Kernel 4: final loss = -var(image, ddof=1)
// ---------------------------------------------------------------------------
__global__ void final_kernel(float* out) {
    const double sum   = g_acc[0];
    const double sumsq = g_acc[1];
    const double Nd    = (double)NIMG;
    const double var   = (sumsq - sum * sum / Nd) / (Nd - 1.0);
    out[0] = (float)(-var);
}

// ---------------------------------------------------------------------------
extern "C" void kernel_launch(void* const* d_in, const int* in_sizes, int n_in,
                              void* d_out, int out_size)
{
    const float* flow;
    const float* spike;
    if (in_sizes[0] == 2 * NPIX) {
        flow  = (const float*)d_in[0];
        spike = (const float*)d_in[1];
    } else {
        flow  = (const float*)d_in[1];
        spike = (const float*)d_in[0];
    }
    float* out = (float*)d_out;

    zero_kernel<<<(NIMG / 4 + 255) / 256, 256>>>();
    splat_kernel<<<(NPIX + 255) / 256, 256>>>(flow, spike);
    reduce_kernel<<<1024, 256>>>();
    final_kernel<<<1, 1>>>(out);
}